// round 1
// baseline (speedup 1.0000x reference)
#include <cuda_runtime.h>
#include <cstdint>

// Problem constants (fixed by the reference):
//   B=4096, T=1024, H=15
// Inputs (metadata order): x[B*T], w_ih[15], w_hh[225], b_ih[15], b_hh[15], w_lin[15], b_lin[1]
// Output: out[B*T] float32
//
// Layout: 16-lane group handles 2 batches packed as f32x2 (lo=even batch, hi=odd batch).
// Lane i (i<15) owns hidden component i; lane 15 computes the linear head as a
// "16th row" (weights = w_lin, bias = b_lin, w_ih = 0), one step delayed.
// Hidden state lives in double-buffered shared memory; 1 __syncwarp per step.

#define T_      1024
#define H_      15
#define TC      128          // time chunk staged in smem
#define NCHUNK  (T_ / TC)
#define THREADS 128          // 4 warps = 8 groups = 16 batches per CTA
#define GROUPS  8
#define BPC     16           // batches per CTA
#define GRID    (4096 / BPC) // 256 CTAs

typedef unsigned long long u64;

__device__ __forceinline__ u64 pk(float lo, float hi) {
    u64 r; asm("mov.b64 %0, {%1, %2};" : "=l"(r) : "f"(lo), "f"(hi)); return r;
}
__device__ __forceinline__ void upk(u64 v, float& lo, float& hi) {
    asm("mov.b64 {%0, %1}, %2;" : "=f"(lo), "=f"(hi) : "l"(v));
}
__device__ __forceinline__ u64 fma2_(u64 a, u64 b, u64 c) {
    u64 d; asm("fma.rn.f32x2 %0, %1, %2, %3;" : "=l"(d) : "l"(a), "l"(b), "l"(c)); return d;
}
__device__ __forceinline__ u64 mul2_(u64 a, u64 b) {
    u64 d; asm("mul.rn.f32x2 %0, %1, %2;" : "=l"(d) : "l"(a), "l"(b)); return d;
}
__device__ __forceinline__ u64 add2_(u64 a, u64 b) {
    u64 d; asm("add.rn.f32x2 %0, %1, %2;" : "=l"(d) : "l"(a), "l"(b)); return d;
}
__device__ __forceinline__ float ex2a(float x) {
    float r; asm("ex2.approx.f32 %0, %1;" : "=f"(r) : "f"(x)); return r;
}
__device__ __forceinline__ float rcpa(float x) {
    float r; asm("rcp.approx.f32 %0, %1;" : "=f"(r) : "f"(x)); return r;
}

// One RNN step for this lane. hr: read buffer (h_{t-1}), hw: write buffer.
// Returns nothing; writes hw[li] and (lane15) the delayed output to osh.
__device__ __forceinline__ void do_step(
    const u64* __restrict__ hr, u64* __restrict__ hw,
    int li, bool is_h, const u64* __restrict__ w2, u64 wih2, u64 bias2,
    u64 xv, float* __restrict__ osr0, float* __restrict__ osr1, int tt,
    u64 C2, u64 ONE2, u64 NEG22)
{
    u64 xp = fma2_(xv, wih2, bias2);
    // 15-term matvec, 3 accumulators (depth ~5)
    u64 a0 = fma2_(w2[0], hr[0], xp);
    u64 a1 = mul2_(w2[1], hr[1]);
    u64 a2 = mul2_(w2[2], hr[2]);
#pragma unroll
    for (int j = 3; j < 15; j += 3) {
        a0 = fma2_(w2[j + 0], hr[j + 0], a0);
        a1 = fma2_(w2[j + 1], hr[j + 1], a1);
        a2 = fma2_(w2[j + 2], hr[j + 2], a2);
    }
    u64 acc = add2_(a0, add2_(a1, a2));

    // tanh(x) = 1 - 2/(exp2(x*2*log2e)+1)   (accurate to ~1e-6; saturates cleanly)
    u64 y = mul2_(acc, C2);
    float y0, y1; upk(y, y0, y1);
    u64 e  = pk(ex2a(y0), ex2a(y1));
    u64 ep = add2_(e, ONE2);
    float p0, p1; upk(ep, p0, p1);
    u64 r  = pk(rcpa(p0), rcpa(p1));
    u64 th = fma2_(NEG22, r, ONE2);

    hw[li] = is_h ? th : acc;          // lane15 slot never read back
    if (!is_h) {                        // lane15: acc == out[t-1] for both batches
        float o0, o1; upk(acc, o0, o1);
        osr0[tt] = o0; osr1[tt] = o1;
    }
    __syncwarp();
}

__global__ void __launch_bounds__(THREADS, 2)
rnn_kernel(const float* __restrict__ x,
           const float* __restrict__ w_ih, const float* __restrict__ w_hh,
           const float* __restrict__ b_ih, const float* __restrict__ b_hh,
           const float* __restrict__ w_lin, const float* __restrict__ b_lin,
           float* __restrict__ out)
{
    __shared__ u64  hbuf[2][GROUPS][17];      // padded: groups 136B apart -> no bank conflicts
    __shared__ u64  xsh[GROUPS][TC + 1];      // packed x pairs per group, padded pitch
    __shared__ float osh[BPC][TC + 1];        // per-batch staged outputs

    const int tid  = threadIdx.x;
    const int lane = tid & 31;
    const int warp = tid >> 5;
    const int li   = lane & 15;
    const int g    = warp * 2 + (lane >> 4);
    const int b0   = blockIdx.x * BPC;
    const bool is_h = (li < 15);

    // Per-lane weights (duplicated into both f32x2 halves)
    u64 w2[15], wih2, bias2;
    if (is_h) {
#pragma unroll
        for (int j = 0; j < 15; j++) { float w = w_hh[li * 15 + j]; w2[j] = pk(w, w); }
        float wi = w_ih[li];               wih2  = pk(wi, wi);
        float bb = b_ih[li] + b_hh[li];    bias2 = pk(bb, bb);
    } else {
#pragma unroll
        for (int j = 0; j < 15; j++) { float w = w_lin[j]; w2[j] = pk(w, w); }
        wih2 = pk(0.0f, 0.0f);
        float bb = b_lin[0];               bias2 = pk(bb, bb);
    }

    const u64 C2    = pk(2.8853900817779268f, 2.8853900817779268f);  // 2*log2(e)
    const u64 ONE2  = pk(1.0f, 1.0f);
    const u64 NEG22 = pk(-2.0f, -2.0f);

    hbuf[0][g][li] = 0ull;                 // h0 = 0

    const float* xrow = x   + (size_t)b0 * T_;
    float*       orow = out + (size_t)b0 * T_;

    float* const osr0 = &osh[2 * g + 0][0];
    float* const osr1 = &osh[2 * g + 1][0];
    const u64* const w2p = w2;

    for (int c = 0; c < NCHUNK; ++c) {
        __syncthreads();  // prior chunk's x reads & osh writes complete

        // Stage x chunk c (coalesced float4 loads, transposed into packed pairs)
#pragma unroll
        for (int it = 0; it < 4; ++it) {
            int idx = tid + it * THREADS;            // 0..511 ; 32 float4 per batch
            int bb  = idx >> 5;
            int k   = idx & 31;
            float4 v = *reinterpret_cast<const float4*>(xrow + (size_t)bb * T_ + c * TC + k * 4);
            float* dst = reinterpret_cast<float*>(&xsh[bb >> 1][0]);
            int half = bb & 1;
            dst[(k * 4 + 0) * 2 + half] = v.x;
            dst[(k * 4 + 1) * 2 + half] = v.y;
            dst[(k * 4 + 2) * 2 + half] = v.z;
            dst[(k * 4 + 3) * 2 + half] = v.w;
        }
        // Flush osh of chunk c-1 (slot s holds out[(c-1)*TC + s - 1])
        if (c > 0) {
#pragma unroll
            for (int it = 0; it < 16; ++it) {
                int idx = tid + it * THREADS;        // 0..2047
                int bb  = idx >> 7;                  // TC = 128
                int s   = idx & 127;
                int gt  = (c - 1) * TC + s - 1;
                if (gt >= 0) orow[(size_t)bb * T_ + gt] = osh[bb][s];
            }
        }
        __syncthreads();

        // TC sequential steps, ping-pong buffers (TC even -> always start on buf0)
#pragma unroll 1
        for (int s = 0; s < TC; s += 2) {
            do_step(&hbuf[0][g][0], &hbuf[1][g][0], li, is_h, w2p, wih2, bias2,
                    xsh[g][s],     osr0, osr1, s,     C2, ONE2, NEG22);
            do_step(&hbuf[1][g][0], &hbuf[0][g][0], li, is_h, w2p, wih2, bias2,
                    xsh[g][s + 1], osr0, osr1, s + 1, C2, ONE2, NEG22);
        }
    }

    __syncthreads();
    // Flush last chunk (slot s holds out[(NCHUNK-1)*TC + s - 1], all >= 0)
#pragma unroll
    for (int it = 0; it < 16; ++it) {
        int idx = tid + it * THREADS;
        int bb  = idx >> 7;
        int s   = idx & 127;
        int gt  = (NCHUNK - 1) * TC + s - 1;
        orow[(size_t)bb * T_ + gt] = osh[bb][s];
    }
    // Epilogue: out[T-1] from final h (in buf0 after 1024 steps)
    if (!is_h) {
        const u64* hr = &hbuf[0][g][0];
        u64 a0 = fma2_(w2[0], hr[0], bias2);
        u64 a1 = mul2_(w2[1], hr[1]);
        u64 a2 = mul2_(w2[2], hr[2]);
#pragma unroll
        for (int j = 3; j < 15; j += 3) {
            a0 = fma2_(w2[j + 0], hr[j + 0], a0);
            a1 = fma2_(w2[j + 1], hr[j + 1], a1);
            a2 = fma2_(w2[j + 2], hr[j + 2], a2);
        }
        u64 acc = add2_(a0, add2_(a1, a2));
        float o0, o1; upk(acc, o0, o1);
        orow[(size_t)(2 * g + 0) * T_ + (T_ - 1)] = o0;
        orow[(size_t)(2 * g + 1) * T_ + (T_ - 1)] = o1;
    }
}

extern "C" void kernel_launch(void* const* d_in, const int* in_sizes, int n_in,
                              void* d_out, int out_size)
{
    const float* x     = (const float*)d_in[0];
    const float* w_ih  = (const float*)d_in[1];
    const float* w_hh  = (const float*)d_in[2];
    const float* b_ih  = (const float*)d_in[3];
    const float* b_hh  = (const float*)d_in[4];
    const float* w_lin = (const float*)d_in[5];
    const float* b_lin = (const float*)d_in[6];
    float* out = (float*)d_out;
    rnn_kernel<<<GRID, THREADS>>>(x, w_ih, w_hh, b_ih, b_hh, w_lin, b_lin, out);
}

// round 3
// speedup vs baseline: 1.4880x; 1.4880x over previous
#include <cuda_runtime.h>
#include <cstdint>

// B=4096, T=1024, H=15
// Inputs: x[B*T], w_ih[15], w_hh[225], b_ih[15], b_hh[15], w_lin[15], b_lin[1]
// Output: out[B*T] float32
//
// 16-lane group handles 2 batches packed as f32x2. Lane i<15 owns hidden
// component i; lane 15 computes the linear head one step delayed.
// h state double-buffered in shared; vectorized LDS.128 broadcast;
// MUFU.TANH; 1 WARPSYNC per step.

#define T_      1024
#define TC      128
#define NCHUNK  (T_ / TC)
#define THREADS 128
#define GROUPS  8
#define BPC     16
#define GRID    (4096 / BPC)
#define HSTRIDE 18            // u64 stride per group: 144B, 16B-aligned, bank-disjoint

typedef unsigned long long u64;

__device__ __forceinline__ u64 pk(float lo, float hi) {
    u64 r; asm("mov.b64 %0, {%1, %2};" : "=l"(r) : "f"(lo), "f"(hi)); return r;
}
__device__ __forceinline__ void upk(u64 v, float& lo, float& hi) {
    asm("mov.b64 {%0, %1}, %2;" : "=f"(lo), "=f"(hi) : "l"(v));
}
__device__ __forceinline__ u64 fma2_(u64 a, u64 b, u64 c) {
    u64 d; asm("fma.rn.f32x2 %0, %1, %2, %3;" : "=l"(d) : "l"(a), "l"(b), "l"(c)); return d;
}
__device__ __forceinline__ u64 mul2_(u64 a, u64 b) {
    u64 d; asm("mul.rn.f32x2 %0, %1, %2;" : "=l"(d) : "l"(a), "l"(b)); return d;
}
__device__ __forceinline__ u64 add2_(u64 a, u64 b) {
    u64 d; asm("add.rn.f32x2 %0, %1, %2;" : "=l"(d) : "l"(a), "l"(b)); return d;
}
__device__ __forceinline__ float tanha(float x) {
    float r; asm("tanh.approx.f32 %0, %1;" : "=f"(r) : "f"(x)); return r;
}

__device__ __forceinline__ void do_step(
    const u64* __restrict__ hr, u64* __restrict__ hw,
    int li, bool is_h, const u64* __restrict__ w2, u64 wih2, u64 bias2,
    u64 xv, u64* __restrict__ osr, int tt)
{
    // Broadcast-load h_{t-1}: 7x LDS.128 + 1x LDS.64
    u64 h[15];
#pragma unroll
    for (int j = 0; j < 14; j += 2) {
        ulonglong2 v = *reinterpret_cast<const ulonglong2*>(hr + j);
        h[j] = v.x; h[j + 1] = v.y;
    }
    h[14] = hr[14];

    u64 xp = fma2_(xv, wih2, bias2);
    u64 a0 = fma2_(w2[0], h[0], xp);
    u64 a1 = mul2_(w2[1], h[1]);
    u64 a2 = mul2_(w2[2], h[2]);
#pragma unroll
    for (int j = 3; j < 15; j += 3) {
        a0 = fma2_(w2[j + 0], h[j + 0], a0);
        a1 = fma2_(w2[j + 1], h[j + 1], a1);
        a2 = fma2_(w2[j + 2], h[j + 2], a2);
    }
    u64 acc = add2_(a0, add2_(a1, a2));

    float y0, y1; upk(acc, y0, y1);
    u64 th = pk(tanha(y0), tanha(y1));

    hw[li] = th;                 // lane15's slot is never read back
    if (!is_h) osr[tt] = acc;    // packed head output for t-1 (both batches)
    __syncwarp();
}

__global__ void __launch_bounds__(THREADS, 2)
rnn_kernel(const float* __restrict__ x,
           const float* __restrict__ w_ih, const float* __restrict__ w_hh,
           const float* __restrict__ b_ih, const float* __restrict__ b_hh,
           const float* __restrict__ w_lin, const float* __restrict__ b_lin,
           float* __restrict__ out)
{
    __shared__ __align__(16) u64 hbuf[2][GROUPS][HSTRIDE];
    __shared__ u64 xsh[GROUPS][TC + 1];      // packed x pairs per group
    __shared__ u64 osh[GROUPS][TC + 1];      // packed head outputs per group

    const int tid  = threadIdx.x;
    const int lane = tid & 31;
    const int warp = tid >> 5;
    const int li   = lane & 15;
    const int g    = warp * 2 + (lane >> 4);
    const int b0   = blockIdx.x * BPC;
    const bool is_h = (li < 15);

    u64 w2[15], wih2, bias2;
    if (is_h) {
#pragma unroll
        for (int j = 0; j < 15; j++) { float w = w_hh[li * 15 + j]; w2[j] = pk(w, w); }
        float wi = w_ih[li];               wih2  = pk(wi, wi);
        float bb = b_ih[li] + b_hh[li];    bias2 = pk(bb, bb);
    } else {
#pragma unroll
        for (int j = 0; j < 15; j++) { float w = w_lin[j]; w2[j] = pk(w, w); }
        wih2 = pk(0.0f, 0.0f);
        float bb = b_lin[0];               bias2 = pk(bb, bb);
    }

    hbuf[0][g][li] = 0ull;                 // h0 = 0

    const float* xrow = x   + (size_t)b0 * T_;
    float*       orow = out + (size_t)b0 * T_;
    u64* const osr = &osh[g][0];
    const u64* const w2p = w2;

    for (int c = 0; c < NCHUNK; ++c) {
        __syncthreads();  // prior chunk's x reads & osh writes complete

        // Stage x chunk c (coalesced float4 loads, transposed into packed pairs)
#pragma unroll
        for (int it = 0; it < 4; ++it) {
            int idx = tid + it * THREADS;            // 0..511 ; 32 float4 per batch
            int bb  = idx >> 5;
            int k   = idx & 31;
            float4 v = *reinterpret_cast<const float4*>(xrow + (size_t)bb * T_ + c * TC + k * 4);
            float* dst = reinterpret_cast<float*>(&xsh[bb >> 1][0]);
            int half = bb & 1;
            dst[(k * 4 + 0) * 2 + half] = v.x;
            dst[(k * 4 + 1) * 2 + half] = v.y;
            dst[(k * 4 + 2) * 2 + half] = v.z;
            dst[(k * 4 + 3) * 2 + half] = v.w;
        }
        // Flush osh of chunk c-1 (slot s holds out[(c-1)*TC + s - 1])
        if (c > 0) {
#pragma unroll
            for (int it = 0; it < 16; ++it) {
                int idx = tid + it * THREADS;        // 0..2047
                int bb  = idx >> 7;
                int s   = idx & 127;
                int gt  = (c - 1) * TC + s - 1;
                float v = reinterpret_cast<const float*>(&osh[bb >> 1][0])[2 * s + (bb & 1)];
                if (gt >= 0) orow[(size_t)bb * T_ + gt] = v;
            }
        }
        __syncthreads();

        // TC sequential steps, ping-pong buffers
#pragma unroll 1
        for (int s = 0; s < TC; s += 2) {
            do_step(&hbuf[0][g][0], &hbuf[1][g][0], li, is_h, w2p, wih2, bias2,
                    xsh[g][s],     osr, s);
            do_step(&hbuf[1][g][0], &hbuf[0][g][0], li, is_h, w2p, wih2, bias2,
                    xsh[g][s + 1], osr, s + 1);
        }
    }

    __syncthreads();
    // Flush last chunk
#pragma unroll
    for (int it = 0; it < 16; ++it) {
        int idx = tid + it * THREADS;
        int bb  = idx >> 7;
        int s   = idx & 127;
        int gt  = (NCHUNK - 1) * TC + s - 1;
        float v = reinterpret_cast<const float*>(&osh[bb >> 1][0])[2 * s + (bb & 1)];
        orow[(size_t)bb * T_ + gt] = v;
    }
    // Epilogue: out[T-1] from final h (in buf0 after 1024 steps)
    if (!is_h) {
        const u64* hr = &hbuf[0][g][0];
        u64 a0 = fma2_(w2[0], hr[0], bias2);
        u64 a1 = mul2_(w2[1], hr[1]);
        u64 a2 = mul2_(w2[2], hr[2]);
#pragma unroll
        for (int j = 3; j < 15; j += 3) {
            a0 = fma2_(w2[j + 0], hr[j + 0], a0);
            a1 = fma2_(w2[j + 1], hr[j + 1], a1);
            a2 = fma2_(w2[j + 2], hr[j + 2], a2);
        }
        u64 acc = add2_(a0, add2_(a1, a2));
        float o0, o1; upk(acc, o0, o1);
        orow[(size_t)(2 * g + 0) * T_ + (T_ - 1)] = o0;
        orow[(size_t)(2 * g + 1) * T_ + (T_ - 1)] = o1;
    }
}

extern "C" void kernel_launch(void* const* d_in, const int* in_sizes, int n_in,
                              void* d_out, int out_size)
{
    const float* x     = (const float*)d_in[0];
    const float* w_ih  = (const float*)d_in[1];
    const float* w_hh  = (const float*)d_in[2];
    const float* b_ih  = (const float*)d_in[3];
    const float* b_hh  = (const float*)d_in[4];
    const float* w_lin = (const float*)d_in[5];
    const float* b_lin = (const float*)d_in[6];
    float* out = (float*)d_out;
    rnn_kernel<<<GRID, THREADS>>>(x, w_ih, w_hh, b_ih, b_hh, w_lin, b_lin, out);
}

// round 4
// speedup vs baseline: 1.7366x; 1.1671x over previous
#include <cuda_runtime.h>
#include <cstdint>

// B=4096, T=1024, H=15
// Inputs: x[B*T], w_ih[15], w_hh[225], b_ih[15], b_hh[15], w_lin[15], b_lin[1]
// Output: out[B*T] float32
//
// Scalar layout: each 16-lane half-warp owns ONE batch. Lane i<15 owns hidden
// component i; lane 15 computes the linear head one step delayed. 2048 warps
// total (3.46/SMSP) to hide the per-step dependency chain.

#define T_      1024
#define TC      128
#define NCHUNK  (T_ / TC)
#define THREADS 64            // 2 warps = 4 half-warp groups = 4 batches per CTA
#define BPC     4
#define GRID    (4096 / BPC)  // 1024 CTAs
#define XPITCH  132           // floats; 528B row: 16B-aligned, bank-shifted by 4

__device__ __forceinline__ float tanha(float x) {
    float r; asm("tanh.approx.f32 %0, %1;" : "=f"(r) : "f"(x)); return r;
}

__device__ __forceinline__ void do_step(
    const float* __restrict__ hr, float* __restrict__ hw,
    int li, const float* __restrict__ w, float wih, float bias,
    float xv, float* __restrict__ osr, int tt, bool is_head)
{
    // Broadcast-load h_{t-1}: 4x LDS.128 (slot 15 is junk, never used)
    float h[16];
#pragma unroll
    for (int j = 0; j < 16; j += 4) {
        float4 v = *reinterpret_cast<const float4*>(hr + j);
        h[j] = v.x; h[j + 1] = v.y; h[j + 2] = v.z; h[j + 3] = v.w;
    }

    float xp = fmaf(xv, wih, bias);
    float a0 = fmaf(w[0], h[0], xp);
    float a1 = w[1] * h[1];
    float a2 = w[2] * h[2];
#pragma unroll
    for (int j = 3; j < 15; j += 3) {
        a0 = fmaf(w[j + 0], h[j + 0], a0);
        a1 = fmaf(w[j + 1], h[j + 1], a1);
        a2 = fmaf(w[j + 2], h[j + 2], a2);
    }
    float acc = a0 + (a1 + a2);

    hw[li] = tanha(acc);          // slot 15 junk, never read
    if (is_head) osr[tt] = acc;   // lane 15: head output for t-1
    __syncwarp();
}

__global__ void __launch_bounds__(THREADS)
rnn_kernel(const float* __restrict__ x,
           const float* __restrict__ w_ih, const float* __restrict__ w_hh,
           const float* __restrict__ b_ih, const float* __restrict__ b_hh,
           const float* __restrict__ w_lin, const float* __restrict__ b_lin,
           float* __restrict__ out)
{
    __shared__ __align__(16) float hbuf[2][BPC][16];   // batches 64B apart
    __shared__ __align__(16) float xsh[BPC][XPITCH];
    __shared__ float osh[BPC][TC + 1];

    const int tid  = threadIdx.x;
    const int lane = tid & 31;
    const int li   = lane & 15;
    const int g    = tid >> 4;          // 0..3: batch within CTA
    const int b0   = blockIdx.x * BPC;
    const bool is_head = (li == 15);

    // Per-lane weights
    float w[15], wih, bias;
    if (!is_head) {
#pragma unroll
        for (int j = 0; j < 15; j++) w[j] = w_hh[li * 15 + j];
        wih  = w_ih[li];
        bias = b_ih[li] + b_hh[li];
    } else {
#pragma unroll
        for (int j = 0; j < 15; j++) w[j] = w_lin[j];
        wih  = 0.0f;
        bias = b_lin[0];
    }

    hbuf[0][g][li] = 0.0f;              // h0 = 0

    const float* xrow = x   + (size_t)b0 * T_;
    float*       orow = out + (size_t)b0 * T_;
    float* const osr  = &osh[g][0];
    const float* hr0 = &hbuf[0][g][0];
    float*       hw0 = &hbuf[0][g][0];
    const float* hr1 = &hbuf[1][g][0];
    float*       hw1 = &hbuf[1][g][0];

    for (int c = 0; c < NCHUNK; ++c) {
        __syncthreads();  // prior chunk's x reads & osh writes complete

        // Stage x chunk c: 4 batches x 128 floats = 128 float4, 64 threads x 2
#pragma unroll
        for (int it = 0; it < 2; ++it) {
            int idx = tid + it * THREADS;           // 0..127
            int bb  = idx >> 5;                     // 0..3
            int k   = idx & 31;                     // float4 index within chunk
            float4 v = *reinterpret_cast<const float4*>(xrow + (size_t)bb * T_ + c * TC + k * 4);
            *reinterpret_cast<float4*>(&xsh[bb][k * 4]) = v;
        }
        // Flush osh of chunk c-1 (slot s holds out[(c-1)*TC + s - 1])
        if (c > 0) {
#pragma unroll
            for (int it = 0; it < 8; ++it) {
                int idx = tid + it * THREADS;       // 0..511
                int bb  = idx >> 7;
                int s   = idx & 127;
                int gt  = (c - 1) * TC + s - 1;
                if (gt >= 0) orow[(size_t)bb * T_ + gt] = osh[bb][s];
            }
        }
        __syncthreads();

        const float* xs = &xsh[g][0];
#pragma unroll 1
        for (int s = 0; s < TC; s += 2) {
            float xv0 = xs[s];
            float xv1 = xs[s + 1];
            do_step(hr0, hw1, li, w, wih, bias, xv0, osr, s,     is_head);
            do_step(hr1, hw0, li, w, wih, bias, xv1, osr, s + 1, is_head);
        }
    }

    __syncthreads();
    // Flush last chunk
#pragma unroll
    for (int it = 0; it < 8; ++it) {
        int idx = tid + it * THREADS;
        int bb  = idx >> 7;
        int s   = idx & 127;
        int gt  = (NCHUNK - 1) * TC + s - 1;
        orow[(size_t)bb * T_ + gt] = osh[bb][s];
    }
    // Epilogue: out[T-1] from final h (in buf0 after 1024 steps)
    if (is_head) {
        const float* hr = hr0;
        float a0 = fmaf(w[0], hr[0], bias);
        float a1 = w[1] * hr[1];
        float a2 = w[2] * hr[2];
#pragma unroll
        for (int j = 3; j < 15; j += 3) {
            a0 = fmaf(w[j + 0], hr[j + 0], a0);
            a1 = fmaf(w[j + 1], hr[j + 1], a1);
            a2 = fmaf(w[j + 2], hr[j + 2], a2);
        }
        orow[(size_t)g * T_ + (T_ - 1)] = a0 + (a1 + a2);
    }
}

extern "C" void kernel_launch(void* const* d_in, const int* in_sizes, int n_in,
                              void* d_out, int out_size)
{
    const float* x     = (const float*)d_in[0];
    const float* w_ih  = (const float*)d_in[1];
    const float* w_hh  = (const float*)d_in[2];
    const float* b_ih  = (const float*)d_in[3];
    const float* b_hh  = (const float*)d_in[4];
    const float* w_lin = (const float*)d_in[5];
    const float* b_lin = (const float*)d_in[6];
    float* out = (float*)d_out;
    rnn_kernel<<<GRID, THREADS>>>(x, w_ih, w_hh, b_ih, b_hh, w_lin, b_lin, out);
}